// round 1
// baseline (speedup 1.0000x reference)
#include <cuda_runtime.h>
#include <cuda_bf16.h>
#include <mma.h>

using namespace nvcuda;

// Problem constants
#define NUM_PARTS     16
#define ROWS_PER_PART 257
#define M_REAL        4112        // 257 * 16 distinct table rows
#define VAE           768
#define OUTD          1024
#define BATCH         4096

// GEMM tiling
#define BM 64
#define BN 128
#define BK 32
#define M_TILES 65                 // ceil(4112/64)
#define M_PAD   (M_TILES * BM)     // 4160
#define GEMM_THREADS 256

// Scratch (device globals: allocation-free per harness rules)
__device__ __nv_bfloat16 g_H[M_PAD * OUTD];   // layer-1 activations (bf16)
__device__ float         g_T[M_PAD * OUTD];   // final table: proj + pe

// ---------------------------------------------------------------------------
// Fused table GEMM:
//   LAYER==1: g_H = relu(emb @ W1 + b1)          (A = emb fp32, C bf16)
//   LAYER==2: g_T = g_H @ W2 + b2 + pe[row/257]  (A = g_H bf16, C fp32)
// C = A[M, K] @ B[K, 1024], B row-major.
// ---------------------------------------------------------------------------
template<int LAYER>
__global__ __launch_bounds__(GEMM_THREADS)
void mlp_gemm(const float* __restrict__ Afloat,
              const float* __restrict__ B,
              const float* __restrict__ bias,
              const float* __restrict__ pe)
{
    constexpr int K = (LAYER == 1) ? VAE : OUTD;

    __shared__ __nv_bfloat16 sA[BM][BK + 16];   // row = 96 B (32B-aligned rows)
    __shared__ __nv_bfloat16 sB[BK][BN + 16];   // row = 288 B
    __shared__ float         sC[BM][BN];

    const int t  = threadIdx.x;
    const int m0 = blockIdx.y * BM;
    const int n0 = blockIdx.x * BN;
    const int w  = t >> 5;
    const int wm = (w & 1) * 32;   // warp row offset within tile
    const int wn = (w >> 1) * 32;  // warp col offset within tile

    wmma::fragment<wmma::accumulator, 16, 16, 16, float> acc[2][2];
    #pragma unroll
    for (int i = 0; i < 2; i++)
        #pragma unroll
        for (int j = 0; j < 2; j++)
            wmma::fill_fragment(acc[i][j], 0.0f);

    for (int k0 = 0; k0 < K; k0 += BK) {
        // ---- load A tile into smem (as bf16) ----
        if (LAYER == 1) {
            #pragma unroll
            for (int i = 0; i < 2; i++) {
                int idx = t + i * GEMM_THREADS;       // 0..511
                int r   = idx >> 3;                   // 0..63
                int c   = (idx & 7) << 2;             // 0,4,...,28
                int ar  = m0 + r; if (ar > M_REAL - 1) ar = M_REAL - 1;  // clamp pad rows
                float4 v = *reinterpret_cast<const float4*>(Afloat + (size_t)ar * K + (k0 + c));
                sA[r][c + 0] = __float2bfloat16(v.x);
                sA[r][c + 1] = __float2bfloat16(v.y);
                sA[r][c + 2] = __float2bfloat16(v.z);
                sA[r][c + 3] = __float2bfloat16(v.w);
            }
        } else {
            int r = t >> 2;               // 0..63
            int c = (t & 3) << 3;         // 0,8,16,24
            const uint4* src = reinterpret_cast<const uint4*>(
                g_H + (size_t)(m0 + r) * OUTD + (k0 + c));   // m0+r < M_PAD always
            *reinterpret_cast<uint4*>(&sA[r][c]) = *src;
        }

        // ---- load B tile (fp32 -> bf16) ----
        #pragma unroll
        for (int i = 0; i < 4; i++) {
            int idx = t + i * GEMM_THREADS;   // 0..1023
            int r   = idx >> 5;               // 0..31
            int c   = (idx & 31) << 2;        // 0..124
            float4 v = *reinterpret_cast<const float4*>(B + (size_t)(k0 + r) * OUTD + (n0 + c));
            sB[r][c + 0] = __float2bfloat16(v.x);
            sB[r][c + 1] = __float2bfloat16(v.y);
            sB[r][c + 2] = __float2bfloat16(v.z);
            sB[r][c + 3] = __float2bfloat16(v.w);
        }
        __syncthreads();

        // ---- MMA ----
        #pragma unroll
        for (int kk = 0; kk < BK; kk += 16) {
            wmma::fragment<wmma::matrix_a, 16, 16, 16, __nv_bfloat16, wmma::row_major> af[2];
            wmma::fragment<wmma::matrix_b, 16, 16, 16, __nv_bfloat16, wmma::row_major> bf[2];
            #pragma unroll
            for (int i = 0; i < 2; i++)
                wmma::load_matrix_sync(af[i], &sA[wm + i * 16][kk], BK + 16);
            #pragma unroll
            for (int j = 0; j < 2; j++)
                wmma::load_matrix_sync(bf[j], &sB[kk][wn + j * 16], BN + 16);
            #pragma unroll
            for (int i = 0; i < 2; i++)
                #pragma unroll
                for (int j = 0; j < 2; j++)
                    wmma::mma_sync(acc[i][j], af[i], bf[j], acc[i][j]);
        }
        __syncthreads();
    }

    // ---- epilogue: acc -> sC -> (bias, relu/pe) -> gmem ----
    #pragma unroll
    for (int i = 0; i < 2; i++)
        #pragma unroll
        for (int j = 0; j < 2; j++)
            wmma::store_matrix_sync(&sC[wm + i * 16][wn + j * 16], acc[i][j], BN,
                                    wmma::mem_row_major);
    __syncthreads();

    const int c4 = (t & 31);           // fixed column (float4 granularity) per thread
    const int gc = n0 + c4 * 4;
    const float4 bias4 = *reinterpret_cast<const float4*>(bias + gc);

    #pragma unroll
    for (int i = 0; i < 8; i++) {
        int r  = (t >> 5) + i * 8;     // 0..63
        int gr = m0 + r;               // < M_PAD
        float4 v = *reinterpret_cast<const float4*>(&sC[r][c4 * 4]);
        v.x += bias4.x; v.y += bias4.y; v.z += bias4.z; v.w += bias4.w;
        if (LAYER == 1) {
            v.x = fmaxf(v.x, 0.0f); v.y = fmaxf(v.y, 0.0f);
            v.z = fmaxf(v.z, 0.0f); v.w = fmaxf(v.w, 0.0f);
            __nv_bfloat162 lo = __floats2bfloat162_rn(v.x, v.y);
            __nv_bfloat162 hi = __floats2bfloat162_rn(v.z, v.w);
            uint2 packed;
            packed.x = *reinterpret_cast<unsigned int*>(&lo);
            packed.y = *reinterpret_cast<unsigned int*>(&hi);
            *reinterpret_cast<uint2*>(g_H + (size_t)gr * OUTD + gc) = packed;
        } else {
            int p = gr / ROWS_PER_PART; if (p > NUM_PARTS - 1) p = NUM_PARTS - 1;
            const float4 pe4 = *reinterpret_cast<const float4*>(pe + (size_t)p * OUTD + gc);
            v.x += pe4.x; v.y += pe4.y; v.z += pe4.z; v.w += pe4.w;
            *reinterpret_cast<float4*>(g_T + (size_t)gr * OUTD + gc) = v;
        }
    }
}

// ---------------------------------------------------------------------------
// Expand: out[b,p,:] = g_T[hash[b,p] + 257*p, :]
// One block per (b,p); 256 threads x float4 = 1024 floats.
// __stcs on stores: output is streamed once, keep the table L2-resident.
// ---------------------------------------------------------------------------
__global__ __launch_bounds__(256)
void expand_kernel(const int* __restrict__ hashes, float* __restrict__ out)
{
    const int bp = blockIdx.x;                 // b*16 + p
    const int p  = bp & (NUM_PARTS - 1);
    const int h  = __ldg(hashes + bp);
    const float4* src = reinterpret_cast<const float4*>(
        g_T + (size_t)(h + p * ROWS_PER_PART) * OUTD);
    float4* dst = reinterpret_cast<float4*>(out) + (size_t)bp * (OUTD / 4);
    __stcs(dst + threadIdx.x, src[threadIdx.x]);
}

// ---------------------------------------------------------------------------
extern "C" void kernel_launch(void* const* d_in, const int* in_sizes, int n_in,
                              void* d_out, int out_size)
{
    // Defensive mapping by element counts (biases disambiguated by order).
    const int*   hashes = nullptr;
    const float* emb = nullptr; const float* W1 = nullptr; const float* W2 = nullptr;
    const float* pe  = nullptr; const float* b1 = nullptr; const float* b2 = nullptr;
    for (int i = 0; i < n_in; i++) {
        switch (in_sizes[i]) {
            case BATCH * NUM_PARTS:      hashes = (const int*)d_in[i];  break; // 65536
            case M_REAL * VAE:           emb    = (const float*)d_in[i]; break; // 3158016
            case VAE * OUTD:             W1     = (const float*)d_in[i]; break; // 786432
            case OUTD * OUTD:            W2     = (const float*)d_in[i]; break; // 1048576
            case NUM_PARTS * OUTD:       pe     = (const float*)d_in[i]; break; // 16384
            case OUTD:
                if (!b1) b1 = (const float*)d_in[i]; else b2 = (const float*)d_in[i];
                break;
            default: break;
        }
    }
    float* out = (float*)d_out;

    dim3 grid(OUTD / BN, M_TILES);   // (8, 65)
    mlp_gemm<1><<<grid, GEMM_THREADS>>>(emb, W1, b1, nullptr);
    mlp_gemm<2><<<grid, GEMM_THREADS>>>(nullptr, W2, b2, pe);
    expand_kernel<<<BATCH * NUM_PARTS, 256>>>(hashes, out);
    (void)out_size;
}

// round 2
// speedup vs baseline: 1.4883x; 1.4883x over previous
#include <cuda_runtime.h>
#include <cuda_bf16.h>
#include <mma.h>

using namespace nvcuda;

// Problem constants
#define NUM_PARTS     16
#define ROWS_PER_PART 257
#define M_REAL        4112        // 257 * 16 distinct table rows
#define VAE           768
#define OUTD          1024
#define BATCH         4096

// GEMM tiling
#define BM 128
#define BN 128
#define BK 64
#define M_TILES 33                 // ceil(4112/128)
#define M_PAD   (M_TILES * BM)     // 4224
#define GEMM_THREADS 256

#define STRIDE_A (BK + 8)          // 72 elems (144B rows, 16B aligned, conflict-free ldmatrix)
#define STRIDE_B (BN + 8)          // 136 elems (272B rows)
#define SMEM_A_BYTES (BM * STRIDE_A * 2)   // 18432
#define SMEM_B_BYTES (BK * STRIDE_B * 2)   // 17408
#define STAGE_BYTES  (SMEM_A_BYTES + SMEM_B_BYTES)
#define GEMM_SMEM    (2 * STAGE_BYTES)     // 71680 > 128*128*4 epilogue reuse OK

// Device-global scratch (allocation-free)
__device__ __nv_bfloat16 g_A [M_PAD * VAE];    // emb, bf16, zero-padded rows
__device__ __nv_bfloat16 g_W1[VAE * OUTD];
__device__ __nv_bfloat16 g_W2[OUTD * OUTD];
__device__ __nv_bfloat16 g_H [M_PAD * OUTD];   // layer-1 activations
__device__ float         g_T [M_PAD * OUTD];   // final table (proj + pe)

// ---------------------------------------------------------------------------
__device__ __forceinline__ void cp_async16(void* smem, const void* gmem) {
    unsigned s = (unsigned)__cvta_generic_to_shared(smem);
    asm volatile("cp.async.cg.shared.global [%0], [%1], 16;\n" :: "r"(s), "l"(gmem));
}
__device__ __forceinline__ void cp_commit() { asm volatile("cp.async.commit_group;\n"); }
__device__ __forceinline__ void cp_wait0()  { asm volatile("cp.async.wait_group 0;\n"); }

__device__ __forceinline__ unsigned pack2(float a, float b) {
    __nv_bfloat162 t = __floats2bfloat162_rn(a, b);
    return *reinterpret_cast<unsigned*>(&t);
}

// ---------------------------------------------------------------------------
// One-shot fp32 -> bf16 conversion of emb (padded), W1, W2.
// ---------------------------------------------------------------------------
__global__ __launch_bounds__(256)
void convert_all(const float* __restrict__ emb,
                 const float* __restrict__ W1,
                 const float* __restrict__ W2)
{
    const int U1 = (M_PAD * VAE) / 4;     // 811008
    const int U2 = (VAE * OUTD) / 4;      // 196608
    const int U3 = (OUTD * OUTD) / 4;     // 262144
    const int UT = U1 + U2 + U3;
    for (int u = blockIdx.x * blockDim.x + threadIdx.x; u < UT;
         u += gridDim.x * blockDim.x) {
        float4 v;
        __nv_bfloat16* dst;
        if (u < U1) {
            int e = u * 4;
            int row = e / VAE;
            if (row < M_REAL) v = *reinterpret_cast<const float4*>(emb + e);
            else              v = make_float4(0.f, 0.f, 0.f, 0.f);
            dst = g_A + e;
        } else if (u < U1 + U2) {
            int e = (u - U1) * 4;
            v = *reinterpret_cast<const float4*>(W1 + e);
            dst = g_W1 + e;
        } else {
            int e = (u - U1 - U2) * 4;
            v = *reinterpret_cast<const float4*>(W2 + e);
            dst = g_W2 + e;
        }
        uint2 p;
        p.x = pack2(v.x, v.y);
        p.y = pack2(v.z, v.w);
        *reinterpret_cast<uint2*>(dst) = p;
    }
}

// ---------------------------------------------------------------------------
// Pipelined bf16 GEMM: C[M_PAD, 1024] = A[M_PAD, K] @ B[K, 1024]
//   IS_L1: A=g_A(K=768),  B=g_W1, epilogue relu -> g_H (bf16)
//   else : A=g_H(K=1024), B=g_W2, epilogue + pe  -> g_T (fp32)
// BM=128, BN=128, BK=64, double-buffered cp.async, 8 warps of 64x32.
// ---------------------------------------------------------------------------
template<int K, bool IS_L1>
__global__ __launch_bounds__(GEMM_THREADS)
void gemm_kern(const float* __restrict__ bias, const float* __restrict__ pe)
{
    extern __shared__ char smem[];
    const __nv_bfloat16* __restrict__ A  = IS_L1 ? g_A  : g_H;
    const __nv_bfloat16* __restrict__ Bw = IS_L1 ? g_W1 : g_W2;

    const int t  = threadIdx.x;
    const int m0 = blockIdx.y * BM;
    const int n0 = blockIdx.x * BN;
    const int w  = t >> 5;
    const int wm = (w >> 2) * 64;   // 2 warp-rows
    const int wn = (w & 3) * 32;    // 4 warp-cols

    wmma::fragment<wmma::accumulator, 16, 16, 16, float> acc[4][2];
    #pragma unroll
    for (int i = 0; i < 4; i++)
        #pragma unroll
        for (int j = 0; j < 2; j++)
            wmma::fill_fragment(acc[i][j], 0.0f);

    auto load_stage = [&](int s, int k0) {
        __nv_bfloat16* sA = (__nv_bfloat16*)(smem + s * STAGE_BYTES);
        __nv_bfloat16* sB = (__nv_bfloat16*)(smem + s * STAGE_BYTES + SMEM_A_BYTES);
        #pragma unroll
        for (int i = 0; i < 4; i++) {               // A: 1024 16B-chunks
            int ch = t + i * GEMM_THREADS;
            int r = ch >> 3, c8 = (ch & 7) * 8;
            cp_async16(sA + r * STRIDE_A + c8,
                       A + (size_t)(m0 + r) * K + k0 + c8);
        }
        #pragma unroll
        for (int i = 0; i < 4; i++) {               // B: 1024 16B-chunks
            int ch = t + i * GEMM_THREADS;
            int r = ch >> 4, c8 = (ch & 15) * 8;
            cp_async16(sB + r * STRIDE_B + c8,
                       Bw + (size_t)(k0 + r) * OUTD + n0 + c8);
        }
        cp_commit();
    };

    constexpr int NIT = K / BK;
    load_stage(0, 0);
    for (int it = 0; it < NIT; it++) {
        cp_wait0();
        __syncthreads();
        if (it + 1 < NIT) load_stage((it + 1) & 1, (it + 1) * BK);

        const __nv_bfloat16* sA = (const __nv_bfloat16*)(smem + (it & 1) * STAGE_BYTES);
        const __nv_bfloat16* sB = (const __nv_bfloat16*)(smem + (it & 1) * STAGE_BYTES + SMEM_A_BYTES);

        #pragma unroll
        for (int kk = 0; kk < BK; kk += 16) {
            wmma::fragment<wmma::matrix_a, 16, 16, 16, __nv_bfloat16, wmma::row_major> af[4];
            wmma::fragment<wmma::matrix_b, 16, 16, 16, __nv_bfloat16, wmma::row_major> bfr[2];
            #pragma unroll
            for (int i = 0; i < 4; i++)
                wmma::load_matrix_sync(af[i], sA + (wm + 16 * i) * STRIDE_A + kk, STRIDE_A);
            #pragma unroll
            for (int j = 0; j < 2; j++)
                wmma::load_matrix_sync(bfr[j], sB + kk * STRIDE_B + wn + 16 * j, STRIDE_B);
            #pragma unroll
            for (int i = 0; i < 4; i++)
                #pragma unroll
                for (int j = 0; j < 2; j++)
                    wmma::mma_sync(acc[i][j], af[i], bfr[j], acc[i][j]);
        }
        __syncthreads();   // protect stage (it&1) from being overwritten next iter
    }

    // ---- epilogue: accums -> smem (as fp32 tile) -> bias/relu/pe -> gmem ----
    float* sC = (float*)smem;   // 128*128*4 = 64KB <= GEMM_SMEM
    #pragma unroll
    for (int i = 0; i < 4; i++)
        #pragma unroll
        for (int j = 0; j < 2; j++)
            wmma::store_matrix_sync(sC + (wm + 16 * i) * BN + wn + 16 * j,
                                    acc[i][j], BN, wmma::mem_row_major);
    __syncthreads();

    const int c4 = t & 31;
    const int gc = n0 + c4 * 4;
    const float4 bias4 = *reinterpret_cast<const float4*>(bias + gc);

    #pragma unroll
    for (int i = 0; i < 16; i++) {
        int r  = (t >> 5) + i * 8;   // 0..127
        int gr = m0 + r;
        float4 v = *reinterpret_cast<const float4*>(sC + r * BN + c4 * 4);
        v.x += bias4.x; v.y += bias4.y; v.z += bias4.z; v.w += bias4.w;
        if (IS_L1) {
            v.x = fmaxf(v.x, 0.f); v.y = fmaxf(v.y, 0.f);
            v.z = fmaxf(v.z, 0.f); v.w = fmaxf(v.w, 0.f);
            uint2 p;
            p.x = pack2(v.x, v.y);
            p.y = pack2(v.z, v.w);
            *reinterpret_cast<uint2*>(g_H + (size_t)gr * OUTD + gc) = p;
        } else {
            int p = gr / ROWS_PER_PART; if (p > NUM_PARTS - 1) p = NUM_PARTS - 1;
            const float4 pe4 = *reinterpret_cast<const float4*>(pe + (size_t)p * OUTD + gc);
            v.x += pe4.x; v.y += pe4.y; v.z += pe4.z; v.w += pe4.w;
            *reinterpret_cast<float4*>(g_T + (size_t)gr * OUTD + gc) = v;
        }
    }
}

// ---------------------------------------------------------------------------
// Expand: out[b,p,:] = g_T[hash[b,p] + 257*p, :]  (table L2-resident; streaming stores)
// ---------------------------------------------------------------------------
__global__ __launch_bounds__(256)
void expand_kernel(const int* __restrict__ hashes, float* __restrict__ out)
{
    const int bp = blockIdx.x;
    const int p  = bp & (NUM_PARTS - 1);
    const int h  = __ldg(hashes + bp);
    const float4* src = reinterpret_cast<const float4*>(
        g_T + (size_t)(h + p * ROWS_PER_PART) * OUTD);
    float4* dst = reinterpret_cast<float4*>(out) + (size_t)bp * (OUTD / 4);
    __stcs(dst + threadIdx.x, src[threadIdx.x]);
}

// ---------------------------------------------------------------------------
extern "C" void kernel_launch(void* const* d_in, const int* in_sizes, int n_in,
                              void* d_out, int out_size)
{
    const int*   hashes = nullptr;
    const float* emb = nullptr; const float* W1 = nullptr; const float* W2 = nullptr;
    const float* pe  = nullptr; const float* b1 = nullptr; const float* b2 = nullptr;
    for (int i = 0; i < n_in; i++) {
        switch (in_sizes[i]) {
            case BATCH * NUM_PARTS: hashes = (const int*)d_in[i];   break;
            case M_REAL * VAE:      emb    = (const float*)d_in[i]; break;
            case VAE * OUTD:        W1     = (const float*)d_in[i]; break;
            case OUTD * OUTD:       W2     = (const float*)d_in[i]; break;
            case NUM_PARTS * OUTD:  pe     = (const float*)d_in[i]; break;
            case OUTD:
                if (!b1) b1 = (const float*)d_in[i]; else b2 = (const float*)d_in[i];
                break;
            default: break;
        }
    }
    float* out = (float*)d_out;

    cudaFuncSetAttribute(gemm_kern<VAE,  true >,
                         cudaFuncAttributeMaxDynamicSharedMemorySize, GEMM_SMEM);
    cudaFuncSetAttribute(gemm_kern<OUTD, false>,
                         cudaFuncAttributeMaxDynamicSharedMemorySize, GEMM_SMEM);

    convert_all<<<2048, 256>>>(emb, W1, W2);
    gemm_kern<VAE,  true ><<<dim3(OUTD / BN, M_TILES), GEMM_THREADS, GEMM_SMEM>>>(b1, nullptr);
    gemm_kern<OUTD, false><<<dim3(OUTD / BN, M_TILES), GEMM_THREADS, GEMM_SMEM>>>(b2, pe);
    expand_kernel<<<BATCH * NUM_PARTS, 256>>>(hashes, out);
    (void)out_size;
}

// round 3
// speedup vs baseline: 1.7328x; 1.1643x over previous
#include <cuda_runtime.h>
#include <cuda_bf16.h>
#include <mma.h>

using namespace nvcuda;

// Problem constants
#define NUM_PARTS     16
#define ROWS_PER_PART 257
#define M_REAL        4112        // 257 * 16 distinct table rows
#define VAE           768
#define OUTD          1024
#define BATCH         4096

// GEMM tiling: 128x256 block tile, 512 threads (16 warps of 64x32), single wave
#define BM 128
#define BN 256
#define BK 64
#define M_TILES 33                 // ceil(4112/128)
#define M_PAD   (M_TILES * BM)     // 4224
#define GEMM_THREADS 512

#define STRIDE_A (BK + 8)          // 72
#define STRIDE_B (BN + 8)          // 264
#define SMEM_A_BYTES (BM * STRIDE_A * 2)   // 18432
#define SMEM_B_BYTES (BK * STRIDE_B * 2)   // 33792
#define STAGE_BYTES  (SMEM_A_BYTES + SMEM_B_BYTES)   // 52224
#define EPI_BYTES    (BM * BN * 4)                   // 131072
#define GEMM_SMEM    (EPI_BYTES > 2 * STAGE_BYTES ? EPI_BYTES : 2 * STAGE_BYTES)

// Device-global scratch (allocation-free)
__device__ __nv_bfloat16 g_A [M_PAD * VAE];
__device__ __nv_bfloat16 g_W1[VAE * OUTD];
__device__ __nv_bfloat16 g_W2[OUTD * OUTD];
__device__ __nv_bfloat16 g_H [M_PAD * OUTD];
__device__ float         g_T [M_PAD * OUTD];

// ---------------------------------------------------------------------------
__device__ __forceinline__ void cp_async16(void* smem, const void* gmem) {
    unsigned s = (unsigned)__cvta_generic_to_shared(smem);
    asm volatile("cp.async.cg.shared.global [%0], [%1], 16;\n" :: "r"(s), "l"(gmem));
}
__device__ __forceinline__ void cp_commit() { asm volatile("cp.async.commit_group;\n"); }
__device__ __forceinline__ void cp_wait0()  { asm volatile("cp.async.wait_group 0;\n"); }

__device__ __forceinline__ unsigned pack2(float a, float b) {
    __nv_bfloat162 t = __floats2bfloat162_rn(a, b);
    return *reinterpret_cast<unsigned*>(&t);
}

// ---------------------------------------------------------------------------
__global__ __launch_bounds__(256)
void convert_all(const float* __restrict__ emb,
                 const float* __restrict__ W1,
                 const float* __restrict__ W2)
{
    const int U1 = (M_PAD * VAE) / 4;
    const int U2 = (VAE * OUTD) / 4;
    const int U3 = (OUTD * OUTD) / 4;
    const int UT = U1 + U2 + U3;
    for (int u = blockIdx.x * blockDim.x + threadIdx.x; u < UT;
         u += gridDim.x * blockDim.x) {
        float4 v;
        __nv_bfloat16* dst;
        if (u < U1) {
            int e = u * 4;
            int row = e / VAE;
            if (row < M_REAL) v = *reinterpret_cast<const float4*>(emb + e);
            else              v = make_float4(0.f, 0.f, 0.f, 0.f);
            dst = g_A + e;
        } else if (u < U1 + U2) {
            int e = (u - U1) * 4;
            v = *reinterpret_cast<const float4*>(W1 + e);
            dst = g_W1 + e;
        } else {
            int e = (u - U1 - U2) * 4;
            v = *reinterpret_cast<const float4*>(W2 + e);
            dst = g_W2 + e;
        }
        uint2 p;
        p.x = pack2(v.x, v.y);
        p.y = pack2(v.z, v.w);
        *reinterpret_cast<uint2*>(dst) = p;
    }
}

// ---------------------------------------------------------------------------
// Pipelined bf16 GEMM: C[M_PAD, 1024] = A[M_PAD, K] @ B[K, 1024]
// ---------------------------------------------------------------------------
template<int K, bool IS_L1>
__global__ __launch_bounds__(GEMM_THREADS)
void gemm_kern(const float* __restrict__ bias, const float* __restrict__ pe)
{
    extern __shared__ char smem[];
    const __nv_bfloat16* __restrict__ A  = IS_L1 ? g_A  : g_H;
    const __nv_bfloat16* __restrict__ Bw = IS_L1 ? g_W1 : g_W2;

    const int t  = threadIdx.x;
    const int m0 = blockIdx.y * BM;
    const int n0 = blockIdx.x * BN;
    const int w  = t >> 5;
    const int wm = (w >> 3) * 64;   // 2 warp-rows  (128/64)
    const int wn = (w & 7) * 32;    // 8 warp-cols  (256/32)

    wmma::fragment<wmma::accumulator, 16, 16, 16, float> acc[4][2];
    #pragma unroll
    for (int i = 0; i < 4; i++)
        #pragma unroll
        for (int j = 0; j < 2; j++)
            wmma::fill_fragment(acc[i][j], 0.0f);

    auto load_stage = [&](int s, int k0) {
        __nv_bfloat16* sA = (__nv_bfloat16*)(smem + s * STAGE_BYTES);
        __nv_bfloat16* sB = (__nv_bfloat16*)(smem + s * STAGE_BYTES + SMEM_A_BYTES);
        #pragma unroll
        for (int i = 0; i < 2; i++) {               // A: 1024 16B-chunks
            int ch = t + i * GEMM_THREADS;
            int r = ch >> 3, c8 = (ch & 7) * 8;
            cp_async16(sA + r * STRIDE_A + c8,
                       A + (size_t)(m0 + r) * K + k0 + c8);
        }
        #pragma unroll
        for (int i = 0; i < 4; i++) {               // B: 2048 16B-chunks
            int ch = t + i * GEMM_THREADS;
            int r = ch >> 5, c8 = (ch & 31) * 8;
            cp_async16(sB + r * STRIDE_B + c8,
                       Bw + (size_t)(k0 + r) * OUTD + n0 + c8);
        }
        cp_commit();
    };

    constexpr int NIT = K / BK;
    load_stage(0, 0);
    for (int it = 0; it < NIT; it++) {
        cp_wait0();
        __syncthreads();
        if (it + 1 < NIT) load_stage((it + 1) & 1, (it + 1) * BK);

        const __nv_bfloat16* sA = (const __nv_bfloat16*)(smem + (it & 1) * STAGE_BYTES);
        const __nv_bfloat16* sB = (const __nv_bfloat16*)(smem + (it & 1) * STAGE_BYTES + SMEM_A_BYTES);

        #pragma unroll
        for (int kk = 0; kk < BK; kk += 16) {
            wmma::fragment<wmma::matrix_a, 16, 16, 16, __nv_bfloat16, wmma::row_major> af[4];
            wmma::fragment<wmma::matrix_b, 16, 16, 16, __nv_bfloat16, wmma::row_major> bfr[2];
            #pragma unroll
            for (int i = 0; i < 4; i++)
                wmma::load_matrix_sync(af[i], sA + (wm + 16 * i) * STRIDE_A + kk, STRIDE_A);
            #pragma unroll
            for (int j = 0; j < 2; j++)
                wmma::load_matrix_sync(bfr[j], sB + kk * STRIDE_B + wn + 16 * j, STRIDE_B);
            #pragma unroll
            for (int i = 0; i < 4; i++)
                #pragma unroll
                for (int j = 0; j < 2; j++)
                    wmma::mma_sync(acc[i][j], af[i], bfr[j], acc[i][j]);
        }
        __syncthreads();
    }

    // ---- epilogue ----
    float* sC = (float*)smem;   // 128*256*4 = 131072 <= GEMM_SMEM
    #pragma unroll
    for (int i = 0; i < 4; i++)
        #pragma unroll
        for (int j = 0; j < 2; j++)
            wmma::store_matrix_sync(sC + (wm + 16 * i) * BN + wn + 16 * j,
                                    acc[i][j], BN, wmma::mem_row_major);
    __syncthreads();

    const int c4 = t & 63;             // 64 float4 columns
    const int gc = n0 + c4 * 4;
    const float4 bias4 = *reinterpret_cast<const float4*>(bias + gc);

    #pragma unroll
    for (int i = 0; i < 16; i++) {
        int r  = (t >> 6) + i * 8;     // 0..127
        int gr = m0 + r;
        float4 v = *reinterpret_cast<const float4*>(sC + r * BN + c4 * 4);
        v.x += bias4.x; v.y += bias4.y; v.z += bias4.z; v.w += bias4.w;
        if (IS_L1) {
            v.x = fmaxf(v.x, 0.f); v.y = fmaxf(v.y, 0.f);
            v.z = fmaxf(v.z, 0.f); v.w = fmaxf(v.w, 0.f);
            uint2 p;
            p.x = pack2(v.x, v.y);
            p.y = pack2(v.z, v.w);
            *reinterpret_cast<uint2*>(g_H + (size_t)gr * OUTD + gc) = p;
        } else {
            int p = gr / ROWS_PER_PART; if (p > NUM_PARTS - 1) p = NUM_PARTS - 1;
            const float4 pe4 = *reinterpret_cast<const float4*>(pe + (size_t)p * OUTD + gc);
            v.x += pe4.x; v.y += pe4.y; v.z += pe4.z; v.w += pe4.w;
            *reinterpret_cast<float4*>(g_T + (size_t)gr * OUTD + gc) = v;
        }
    }
}

// ---------------------------------------------------------------------------
// Expand: grid-stride, 4 independent gather chains per thread (MLP=4).
// out[b,p,:] = g_T[hash[b,p] + 257*p, :]
// ---------------------------------------------------------------------------
#define EXP_BLOCKS  1184          // 8 per SM
#define EXP_THREADS 256

__global__ __launch_bounds__(EXP_THREADS)
void expand_kernel(const int* __restrict__ hashes, float* __restrict__ out)
{
    const int NV = BATCH * NUM_PARTS * (OUTD / 4);   // 16,777,216 float4
    const int stride = EXP_BLOCKS * EXP_THREADS;     // 303104
    float4* __restrict__ o4 = reinterpret_cast<float4*>(out);

    for (int base = blockIdx.x * EXP_THREADS + threadIdx.x; base < NV;
         base += 4 * stride) {
        int   idx[4];
        const float4* src[4];
        bool  ok[4];
        #pragma unroll
        for (int u = 0; u < 4; u++) {
            idx[u] = base + u * stride;
            ok[u]  = idx[u] < NV;
            int bp = ok[u] ? (idx[u] >> 8) : 0;
            int p  = bp & (NUM_PARTS - 1);
            int h  = __ldg(hashes + bp);
            src[u] = reinterpret_cast<const float4*>(
                g_T + (size_t)(h + p * ROWS_PER_PART) * OUTD) + (idx[u] & 255);
        }
        float4 v[4];
        #pragma unroll
        for (int u = 0; u < 4; u++)
            if (ok[u]) v[u] = __ldg(src[u]);
        #pragma unroll
        for (int u = 0; u < 4; u++)
            if (ok[u]) __stcs(o4 + idx[u], v[u]);
    }
}

// ---------------------------------------------------------------------------
extern "C" void kernel_launch(void* const* d_in, const int* in_sizes, int n_in,
                              void* d_out, int out_size)
{
    const int*   hashes = nullptr;
    const float* emb = nullptr; const float* W1 = nullptr; const float* W2 = nullptr;
    const float* pe  = nullptr; const float* b1 = nullptr; const float* b2 = nullptr;
    for (int i = 0; i < n_in; i++) {
        switch (in_sizes[i]) {
            case BATCH * NUM_PARTS: hashes = (const int*)d_in[i];   break;
            case M_REAL * VAE:      emb    = (const float*)d_in[i]; break;
            case VAE * OUTD:        W1     = (const float*)d_in[i]; break;
            case OUTD * OUTD:       W2     = (const float*)d_in[i]; break;
            case NUM_PARTS * OUTD:  pe     = (const float*)d_in[i]; break;
            case OUTD:
                if (!b1) b1 = (const float*)d_in[i]; else b2 = (const float*)d_in[i];
                break;
            default: break;
        }
    }
    float* out = (float*)d_out;

    cudaFuncSetAttribute(gemm_kern<VAE,  true >,
                         cudaFuncAttributeMaxDynamicSharedMemorySize, GEMM_SMEM);
    cudaFuncSetAttribute(gemm_kern<OUTD, false>,
                         cudaFuncAttributeMaxDynamicSharedMemorySize, GEMM_SMEM);

    convert_all<<<2048, 256>>>(emb, W1, W2);
    gemm_kern<VAE,  true ><<<dim3(OUTD / BN, M_TILES), GEMM_THREADS, GEMM_SMEM>>>(b1, nullptr);
    gemm_kern<OUTD, false><<<dim3(OUTD / BN, M_TILES), GEMM_THREADS, GEMM_SMEM>>>(b2, pe);
    expand_kernel<<<EXP_BLOCKS, EXP_THREADS>>>(hashes, out);
    (void)out_size;
}